// round 2
// baseline (speedup 1.0000x reference)
#include <cuda_runtime.h>
#include <math.h>

#define W_IMG 128
#define NB 16

// ---------------- scratch (static device globals; no allocation) ----------------
__device__ float g_conv[41943040];   // conv output per stage
__device__ float g_pool[20971520];   // pooled output / next-stage input
__device__ float g_maskA[524288];    // stage input mask (N,1,H,W)
__device__ float g_maskB[524288];    // full-res mask_next before pooling
__device__ float g_stats[1280];      // [sum(0..C), sumsq(C..2C)]
__device__ float g_feat[NB * 640];
__device__ float g_z1[NB * 256];
__device__ float g_z2[NB * 128];

__device__ __forceinline__ unsigned long long fma2(unsigned long long a,
                                                   unsigned long long b,
                                                   unsigned long long c) {
    unsigned long long d;
    asm("fma.rn.f32x2 %0, %1, %2, %3;" : "=l"(d) : "l"(a), "l"(b), "l"(c));
    return d;
}

// ---------------- prep: split data / clipped mask ----------------
__global__ void prep_kernel(const float* __restrict__ x) {
    int idx = blockIdx.x * blockDim.x + threadIdx.x;
    const int per = 256 * 128;
    if (idx >= NB * per) return;
    int n = idx / per;
    int rest = idx - n * per;
    g_pool[idx] = x[(n * 2 + 0) * per + rest];
    float m = x[(n * 2 + 1) * per + rest];
    g_maskA[idx] = fminf(fmaxf(m, 0.f), 1.f);
}

__global__ void zero_stats_kernel(int n) {
    int i = blockIdx.x * blockDim.x + threadIdx.x;
    if (i < n) g_stats[i] = 0.f;
}

// ---------------- partial conv 3x3 (f32x2 packed FMA) ----------------
// block: (h = blockIdx.x, co tile = blockIdx.y*64, n = blockIdx.z)
// 256 threads: 32 pixel-groups (4 px each) x 8 co-groups (8 co each)
// acc packed in pairs along co; weights pair-loaded from smem; inputs stored
// duplicated (v,v) in smem so broadcast pairs are a single LDS.64.
__launch_bounds__(256)
__global__ void pconv_kernel(const float* __restrict__ wts,
                             const float* __restrict__ bias,
                             int Cin, int Cout, int H)
{
    __shared__ __align__(16) float2 s_in2[8][3][132];   // duplicated (v,v)
    __shared__ __align__(16) float  s_m[3][132];
    __shared__ __align__(16) float  s_w[8][9][64];

    const int t    = threadIdx.x;
    const int h    = blockIdx.x;
    const int co0  = blockIdx.y * 64;
    const int n    = blockIdx.z;
    const int pxg  = t & 31;
    const int cog  = t >> 5;       // == warp id
    const int px0  = pxg * 4;
    const int lane = t & 31;

    // ---- mask tile with OOB = 1.0 (mask conv pads with ones) ----
    for (int idx = t; idx < 3 * 130; idx += 256) {
        int r = idx / 130, col = idx % 130;
        int hh = h - 1 + r, ww = col - 1;
        float v = 1.0f;
        if (hh >= 0 && hh < H && ww >= 0 && ww < W_IMG)
            v = g_maskA[(n * H + hh) * W_IMG + ww];
        s_m[r][col] = v;
    }
    __syncthreads();

    float msum[4];
    #pragma unroll
    for (int p = 0; p < 4; p++) {
        float s = 0.f;
        #pragma unroll
        for (int r = 0; r < 3; r++)
            #pragma unroll
            for (int tw = 0; tw < 3; tw++)
                s += s_m[r][px0 + p + tw];
        msum[p] = s;
    }

    // acc2[jp][p]: packed pair over co (j = 2*jp, 2*jp+1), p = pixel 0..3
    unsigned long long acc2[4][4];
    #pragma unroll
    for (int jp = 0; jp < 4; jp++)
        #pragma unroll
        for (int p = 0; p < 4; p++) acc2[jp][p] = 0ull;

    for (int ci0 = 0; ci0 < Cin; ci0 += 8) {
        __syncthreads();
        // input tile: (x * mask) duplicated, OOB = 0
        for (int idx = t; idx < 8 * 3 * 130; idx += 256) {
            int c = idx / 390, rem = idx - c * 390;
            int r = rem / 130, col = rem - r * 130;
            int hh = h - 1 + r, ww = col - 1;
            int ci = ci0 + c;
            float v = 0.f;
            if (ci < Cin && hh >= 0 && hh < H && ww >= 0 && ww < W_IMG)
                v = g_pool[((n * Cin + ci) * H + hh) * W_IMG + ww] * s_m[r][col];
            s_in2[c][r][col] = make_float2(v, v);
        }
        // weight tile
        for (int idx = t; idx < 8 * 9 * 64; idx += 256) {
            int c = idx / 576, rem = idx - c * 576;
            int tap = rem / 64, co = rem - tap * 64;
            int gco = co0 + co, ci = ci0 + c;
            float v = 0.f;
            if (gco < Cout && ci < Cin)
                v = wts[(gco * Cin + ci) * 9 + tap];
            s_w[c][tap][co] = v;
        }
        __syncthreads();

        #pragma unroll
        for (int c = 0; c < 8; c++) {
            #pragma unroll
            for (int r = 0; r < 3; r++) {
                // broadcast input pairs (v,v): one LDS.64 each
                unsigned long long ivp[6];
                #pragma unroll
                for (int k = 0; k < 6; k++)
                    ivp[k] = *(const unsigned long long*)&s_in2[c][r][px0 + k];
                #pragma unroll
                for (int tw = 0; tw < 3; tw++) {
                    // weight pairs along co: two LDS.128 worth of pairs
                    ulonglong2 wA = *(const ulonglong2*)&s_w[c][r * 3 + tw][cog * 8];
                    ulonglong2 wB = *(const ulonglong2*)&s_w[c][r * 3 + tw][cog * 8 + 4];
                    unsigned long long wp[4] = {wA.x, wA.y, wB.x, wB.y};
                    #pragma unroll
                    for (int p = 0; p < 4; p++) {
                        #pragma unroll
                        for (int jp = 0; jp < 4; jp++)
                            acc2[jp][p] = fma2(wp[jp], ivp[tw + p], acc2[jp][p]);
                    }
                }
            }
        }
    }

    // ---- epilogue: scale, bias, zero-invalid, stats, mask_next ----
    float scale[4];
    bool  nov[4];
    #pragma unroll
    for (int p = 0; p < 4; p++) {
        float valid = (float)Cin * msum[p];
        nov[p]   = (valid <= 0.f);
        scale[p] = (float)(Cin * 9) / fmaxf(valid, 1.0f);
    }
    if (blockIdx.y == 0 && cog == 0) {
        #pragma unroll
        for (int p = 0; p < 4; p++)
            g_maskB[(n * H + h) * W_IMG + px0 + p] = nov[p] ? 0.f : 1.f;
    }

    #pragma unroll
    for (int jp = 0; jp < 4; jp++) {
        #pragma unroll
        for (int half = 0; half < 2; half++) {
            int j = 2 * jp + half;
            int gco = co0 + cog * 8 + j;
            bool ok = (gco < Cout);
            float b = ok ? bias[gco] : 0.f;
            float ssum = 0.f, ssq = 0.f;
            #pragma unroll
            for (int p = 0; p < 4; p++) {
                unsigned int bits = half ? (unsigned int)(acc2[jp][p] >> 32)
                                         : (unsigned int)(acc2[jp][p] & 0xffffffffu);
                float a = __uint_as_float(bits);
                float y = nov[p] ? 0.f : (a * scale[p] + b);
                if (ok) g_conv[((n * Cout + gco) * H + h) * W_IMG + px0 + p] = y;
                ssum += y;
                ssq  += y * y;
            }
            #pragma unroll
            for (int off = 16; off; off >>= 1) {
                ssum += __shfl_xor_sync(0xffffffffu, ssum, off);
                ssq  += __shfl_xor_sync(0xffffffffu, ssq,  off);
            }
            if (lane == 0 && ok) {
                atomicAdd(&g_stats[gco], ssum);
                atomicAdd(&g_stats[Cout + gco], ssq);
            }
        }
    }
}

// ---------------- fused BN + ReLU + 2x1 max pool ----------------
__global__ void bn_pool_kernel(const float* __restrict__ gamma,
                               const float* __restrict__ beta,
                               int Cout, int Hc)
{
    int idx = blockIdx.x * blockDim.x + threadIdx.x;
    int Hp = Hc >> 1;
    int total = NB * Cout * Hp * W_IMG;
    if (idx >= total) return;
    int w  = idx % W_IMG;
    int hp = (idx / W_IMG) % Hp;
    int c  = (idx / (W_IMG * Hp)) % Cout;
    int n  = idx / (W_IMG * Hp * Cout);

    float cnt  = (float)(NB * Hc * W_IMG);
    float mean = g_stats[c] / cnt;
    float var  = g_stats[Cout + c] / cnt - mean * mean;
    float inv  = rsqrtf(var + 1e-5f);
    float ga = gamma[c], bb = beta[c];

    int base = ((n * Cout + c) * Hc + 2 * hp) * W_IMG + w;
    float v0 = g_conv[base];
    float v1 = g_conv[base + W_IMG];
    float r0 = fmaxf((v0 - mean) * inv * ga + bb, 0.f);
    float r1 = fmaxf((v1 - mean) * inv * ga + bb, 0.f);
    g_pool[((n * Cout + c) * Hp + hp) * W_IMG + w] = fmaxf(r0, r1);
}

__global__ void mask_pool_kernel(int Hc) {
    int idx = blockIdx.x * blockDim.x + threadIdx.x;
    int Hp = Hc >> 1;
    int total = NB * Hp * W_IMG;
    if (idx >= total) return;
    int w  = idx % W_IMG;
    int hp = (idx / W_IMG) % Hp;
    int n  = idx / (W_IMG * Hp);
    int base = (n * Hc + 2 * hp) * W_IMG + w;
    g_maskA[(n * Hp + hp) * W_IMG + w] = fmaxf(g_maskB[base], g_maskB[base + W_IMG]);
}

// ---------------- head ----------------
__global__ void feat_kernel() {
    __shared__ float sred[128];
    int nc = blockIdx.x;                 // n*640 + c
    const float* p = g_pool + (size_t)nc * 2048;  // 16*128
    float s = 0.f;
    for (int i = threadIdx.x; i < 2048; i += 128) s += p[i];
    sred[threadIdx.x] = s;
    __syncthreads();
    for (int o = 64; o; o >>= 1) {
        if (threadIdx.x < o) sred[threadIdx.x] += sred[threadIdx.x + o];
        __syncthreads();
    }
    if (threadIdx.x == 0) g_feat[nc] = sred[0] * (1.f / 2048.f);
}

__global__ void fc_kernel(const float* __restrict__ Wm, const float* __restrict__ b,
                          const float* __restrict__ in, float* __restrict__ out,
                          int IN, int OUT, int act)   // act: 0=relu, 1=sigmoid
{
    __shared__ float s[640];
    int n = blockIdx.x;
    for (int i = threadIdx.x; i < IN; i += blockDim.x) s[i] = in[n * IN + i];
    __syncthreads();
    int o = threadIdx.x;
    if (o < OUT) {
        float a = b[o];
        const float* wr = Wm + o * IN;
        for (int k = 0; k < IN; k++) a += wr[k] * s[k];
        if (act == 0) a = fmaxf(a, 0.f);
        else          a = 1.f / (1.f + expf(-a));
        out[n * OUT + o] = a;
    }
}

// ---------------- launch ----------------
extern "C" void kernel_launch(void* const* d_in, const int* in_sizes, int n_in,
                              void* d_out, int out_size)
{
    const float* x = (const float*)d_in[0];
    const float* w[4]  = {(const float*)d_in[1],  (const float*)d_in[5],
                          (const float*)d_in[9],  (const float*)d_in[13]};
    const float* bi[4] = {(const float*)d_in[2],  (const float*)d_in[6],
                          (const float*)d_in[10], (const float*)d_in[14]};
    const float* ga[4] = {(const float*)d_in[3],  (const float*)d_in[7],
                          (const float*)d_in[11], (const float*)d_in[15]};
    const float* be[4] = {(const float*)d_in[4],  (const float*)d_in[8],
                          (const float*)d_in[12], (const float*)d_in[16]};
    const float* fw1 = (const float*)d_in[17];
    const float* fb1 = (const float*)d_in[18];
    const float* fw2 = (const float*)d_in[19];
    const float* fb2 = (const float*)d_in[20];
    const float* hw  = (const float*)d_in[21];
    const float* hb  = (const float*)d_in[22];

    float *feat, *z1, *z2;
    cudaGetSymbolAddress((void**)&feat, g_feat);
    cudaGetSymbolAddress((void**)&z1,   g_z1);
    cudaGetSymbolAddress((void**)&z2,   g_z2);

    prep_kernel<<<(NB * 256 * 128 + 255) / 256, 256>>>(x);

    int Cin = 1, H = 256;
    const int Couts[4] = {80, 160, 320, 640};
    for (int s = 0; s < 4; s++) {
        int Cout = Couts[s];
        zero_stats_kernel<<<(2 * Cout + 255) / 256, 256>>>(2 * Cout);
        dim3 grid(H, (Cout + 63) / 64, NB);
        pconv_kernel<<<grid, 256>>>(w[s], bi[s], Cin, Cout, H);
        int Hp = H / 2;
        int total = NB * Cout * Hp * W_IMG;
        bn_pool_kernel<<<(total + 255) / 256, 256>>>(ga[s], be[s], Cout, H);
        mask_pool_kernel<<<(NB * Hp * W_IMG + 255) / 256, 256>>>(H);
        Cin = Cout; H = Hp;
    }

    feat_kernel<<<NB * 640, 128>>>();
    fc_kernel<<<NB, 256>>>(fw1, fb1, feat, z1, 640, 256, 0);
    fc_kernel<<<NB, 256>>>(fw2, fb2, z1, z2, 256, 128, 0);
    fc_kernel<<<NB, 128>>>(hw, hb, z2, (float*)d_out, 128, 1, 1);
}

// round 4
// speedup vs baseline: 2.9363x; 2.9363x over previous
#include <cuda_runtime.h>
#include <cuda_fp16.h>
#include <math.h>
#include <stdint.h>

#define W_IMG 128
#define NB 16
#define LDA 40      // A smem stride in halves (conflict-free for ldmatrix)
#define LDB 136     // B smem stride in halves

// ---------------- scratch (static device globals; no allocation) ----------------
__device__ float  g_conv[41943040];   // conv output per stage
__device__ float  g_pool[20971520];   // pooled output / next-stage input
__device__ float  g_maskA[524288];    // stage input mask (N,1,H,W)
__device__ float  g_maskB[524288];    // full-res mask_next before pooling
__device__ float  g_stats[1280];      // [sum(0..C), sumsq(C..2C)]
__device__ __half g_wTh[1843200];     // transposed+padded fp16 weights [tap][ciP][coP]
__device__ float  g_feat[NB * 640];
__device__ float  g_z1[NB * 256];
__device__ float  g_z2[NB * 128];

__device__ __forceinline__ uint32_t smem_u32(const void* p) {
    uint32_t a;
    asm("{ .reg .u64 t; cvta.to.shared.u64 t, %1; cvt.u32.u64 %0, t; }" : "=r"(a) : "l"(p));
    return a;
}

#define LDMX4(r0, r1, r2, r3, addr) \
    asm volatile("ldmatrix.sync.aligned.m8n8.x4.shared.b16 {%0,%1,%2,%3}, [%4];" \
                 : "=r"(r0), "=r"(r1), "=r"(r2), "=r"(r3) : "r"(addr))
#define LDMX2T(r0, r1, addr) \
    asm volatile("ldmatrix.sync.aligned.m8n8.x2.trans.shared.b16 {%0,%1}, [%2];" \
                 : "=r"(r0), "=r"(r1) : "r"(addr))
#define MMA16816(d, a, b) \
    asm volatile("mma.sync.aligned.m16n8k16.row.col.f32.f16.f16.f32 " \
                 "{%0,%1,%2,%3}, {%4,%5,%6,%7}, {%8,%9}, {%0,%1,%2,%3};" \
                 : "+f"((d)[0]), "+f"((d)[1]), "+f"((d)[2]), "+f"((d)[3]) \
                 : "r"((a)[0]), "r"((a)[1]), "r"((a)[2]), "r"((a)[3]), \
                   "r"((b)[0]), "r"((b)[1]))

// ---------------- prep: split data / clipped mask ----------------
__global__ void prep_kernel(const float* __restrict__ x) {
    int idx = blockIdx.x * blockDim.x + threadIdx.x;
    const int per = 256 * 128;
    if (idx >= NB * per) return;
    int n = idx / per;
    int rest = idx - n * per;
    g_pool[idx] = x[(n * 2 + 0) * per + rest];
    float m = x[(n * 2 + 1) * per + rest];
    g_maskA[idx] = fminf(fmaxf(m, 0.f), 1.f);
}

__global__ void zero_stats_kernel(int n) {
    int i = blockIdx.x * blockDim.x + threadIdx.x;
    if (i < n) g_stats[i] = 0.f;
}

// ---------------- weight transpose+pad: wts[co][ci][tap] -> g_wTh[tap][ci][co] ----------------
__global__ void wprep_kernel(const float* __restrict__ wts,
                             int Cin, int Cinp, int Cout, int CoutP) {
    int idx = blockIdx.x * blockDim.x + threadIdx.x;
    int total = 9 * Cinp * CoutP;
    if (idx >= total) return;
    int tap = idx / (Cinp * CoutP);
    int rem = idx - tap * (Cinp * CoutP);
    int ci = rem / CoutP;
    int co = rem - ci * CoutP;
    float v = 0.f;
    if (ci < Cin && co < Cout) v = wts[(co * Cin + ci) * 9 + tap];
    g_wTh[idx] = __float2half(v);
}

// ---------------- stage-1 scalar partial conv (proven R1, Cin=1) ----------------
__launch_bounds__(256)
__global__ void pconv_kernel(const float* __restrict__ wts,
                             const float* __restrict__ bias,
                             int Cin, int Cout, int H)
{
    __shared__ __align__(16) float s_in[8][3][132];
    __shared__ __align__(16) float s_m[3][132];
    __shared__ __align__(16) float s_w[8][9][64];

    const int t    = threadIdx.x;
    const int h    = blockIdx.x;
    const int co0  = blockIdx.y * 64;
    const int n    = blockIdx.z;
    const int pxg  = t & 31;
    const int cog  = t >> 5;
    const int px0  = pxg * 4;
    const int lane = t & 31;

    for (int idx = t; idx < 3 * 130; idx += 256) {
        int r = idx / 130, col = idx % 130;
        int hh = h - 1 + r, ww = col - 1;
        float v = 1.0f;
        if (hh >= 0 && hh < H && ww >= 0 && ww < W_IMG)
            v = g_maskA[(n * H + hh) * W_IMG + ww];
        s_m[r][col] = v;
    }
    __syncthreads();

    float msum[4];
    #pragma unroll
    for (int p = 0; p < 4; p++) {
        float s = 0.f;
        #pragma unroll
        for (int r = 0; r < 3; r++)
            #pragma unroll
            for (int tw = 0; tw < 3; tw++)
                s += s_m[r][px0 + p + tw];
        msum[p] = s;
    }

    float acc[8][4];
    #pragma unroll
    for (int j = 0; j < 8; j++)
        #pragma unroll
        for (int p = 0; p < 4; p++) acc[j][p] = 0.f;

    for (int ci0 = 0; ci0 < Cin; ci0 += 8) {
        __syncthreads();
        for (int idx = t; idx < 8 * 3 * 130; idx += 256) {
            int c = idx / 390, rem = idx - c * 390;
            int r = rem / 130, col = rem - r * 130;
            int hh = h - 1 + r, ww = col - 1;
            int ci = ci0 + c;
            float v = 0.f;
            if (ci < Cin && hh >= 0 && hh < H && ww >= 0 && ww < W_IMG)
                v = g_pool[((n * Cin + ci) * H + hh) * W_IMG + ww] * s_m[r][col];
            s_in[c][r][col] = v;
        }
        for (int idx = t; idx < 8 * 9 * 64; idx += 256) {
            int c = idx / 576, rem = idx - c * 576;
            int tap = rem / 64, co = rem - tap * 64;
            int gco = co0 + co, ci = ci0 + c;
            float v = 0.f;
            if (gco < Cout && ci < Cin)
                v = wts[(gco * Cin + ci) * 9 + tap];
            s_w[c][tap][co] = v;
        }
        __syncthreads();

        #pragma unroll
        for (int c = 0; c < 8; c++) {
            #pragma unroll
            for (int r = 0; r < 3; r++) {
                float iv[6];
                #pragma unroll
                for (int k = 0; k < 6; k++) iv[k] = s_in[c][r][px0 + k];
                #pragma unroll
                for (int tw = 0; tw < 3; tw++) {
                    float4 wA = *(const float4*)&s_w[c][r * 3 + tw][cog * 8];
                    float4 wB = *(const float4*)&s_w[c][r * 3 + tw][cog * 8 + 4];
                    float wj[8] = {wA.x, wA.y, wA.z, wA.w, wB.x, wB.y, wB.z, wB.w};
                    #pragma unroll
                    for (int j = 0; j < 8; j++)
                        #pragma unroll
                        for (int p = 0; p < 4; p++)
                            acc[j][p] += wj[j] * iv[tw + p];
                }
            }
        }
    }

    float scale[4];
    bool  nov[4];
    #pragma unroll
    for (int p = 0; p < 4; p++) {
        float valid = (float)Cin * msum[p];
        nov[p]   = (valid <= 0.f);
        scale[p] = (float)(Cin * 9) / fmaxf(valid, 1.0f);
    }
    if (blockIdx.y == 0 && cog == 0) {
        #pragma unroll
        for (int p = 0; p < 4; p++)
            g_maskB[(n * H + h) * W_IMG + px0 + p] = nov[p] ? 0.f : 1.f;
    }

    #pragma unroll
    for (int j = 0; j < 8; j++) {
        int gco = co0 + cog * 8 + j;
        bool ok = (gco < Cout);
        float b = ok ? bias[gco] : 0.f;
        float ssum = 0.f, ssq = 0.f;
        #pragma unroll
        for (int p = 0; p < 4; p++) {
            float y = nov[p] ? 0.f : (acc[j][p] * scale[p] + b);
            if (ok) g_conv[((n * Cout + gco) * H + h) * W_IMG + px0 + p] = y;
            ssum += y;
            ssq  += y * y;
        }
        #pragma unroll
        for (int off = 16; off; off >>= 1) {
            ssum += __shfl_xor_sync(0xffffffffu, ssum, off);
            ssq  += __shfl_xor_sync(0xffffffffu, ssq,  off);
        }
        if (lane == 0 && ok) {
            atomicAdd(&g_stats[gco], ssum);
            atomicAdd(&g_stats[Cout + gco], ssq);
        }
    }
}

// ---------------- fp16 HMMA implicit-GEMM partial conv (stages 2-4) ----------------
// CTA: M=128 px (one (n,h) row) x N=128 cout. 8 warps = 2(M) x 4(N), warp tile 64x32.
// K = 9*Cinp in 32-wide fp16 chunks, double-buffered stage-ahead pipeline.
__launch_bounds__(256, 2)
__global__ void pconv_hmma_kernel(const float* __restrict__ bias,
                                  int Cin, int Cinp, int Cout, int H)
{
    __shared__ __align__(16) __half sA[2][128 * LDA];
    __shared__ __align__(16) __half sB[2][32 * LDB];
    __shared__ float s_m[3 * 132];
    __shared__ float s_sc[128];
    __shared__ float s_nv[128];
    __shared__ float s_bi[128];

    const int t    = threadIdx.x;
    const int wid  = t >> 5;
    const int lane = t & 31;
    const int h    = blockIdx.x % H;
    const int n    = blockIdx.x / H;
    const int co0  = blockIdx.y * 128;
    const int CoutP = gridDim.y * 128;
    const int warp_m = wid & 1;        // 0..1 (64 rows each)
    const int warp_n = wid >> 1;       // 0..3 (32 cols each)

    // ---- mask rows (OOB = 1.0) + bias ----
    for (int idx = t; idx < 3 * 130; idx += 256) {
        int r = idx / 130, col = idx % 130;
        int hh = h - 1 + r, ww = col - 1;
        float v = 1.0f;
        if (hh >= 0 && hh < H && ww >= 0 && ww < W_IMG)
            v = g_maskA[(n * H + hh) * W_IMG + ww];
        s_m[r * 132 + col] = v;
    }
    if (t < 128) s_bi[t] = (co0 + t < Cout) ? bias[co0 + t] : 0.f;
    __syncthreads();

    if (t < 128) {
        float s = 0.f;
        #pragma unroll
        for (int r = 0; r < 3; r++)
            #pragma unroll
            for (int tw = 0; tw < 3; tw++)
                s += s_m[r * 132 + t + tw];
        float valid = (float)Cin * s;
        s_nv[t] = (valid <= 0.f) ? 1.f : 0.f;
        s_sc[t] = (float)(Cin * 9) / fmaxf(valid, 1.0f);
        if (blockIdx.y == 0)
            g_maskB[(n * H + h) * W_IMG + t] = (valid <= 0.f) ? 0.f : 1.f;
    }

    const int CPT = Cinp >> 5;
    const int chunks = 9 * CPT;

    // ---- staging lambda-ish macros (manual) ----
    // A: 128m x 32k fp16 (im2col row shifted by tap, x mask)
    // B: 32k x 128n fp16 from g_wTh
    #define STAGE(buf, r_, sc_, ci0_, tap_) do {                                      \
        const int hh_ = h - 1 + (r_);                                                 \
        const bool hok_ = (hh_ >= 0 && hh_ < H);                                      \
        _Pragma("unroll")                                                             \
        for (int i_ = 0; i_ < 8; i_++) {                                              \
            int idx_ = (i_ << 8) + t;                                                 \
            int m_ = idx_ & 127, jp_ = idx_ >> 7;                                     \
            int j0_ = jp_ * 2;                                                        \
            int ww_ = m_ + (sc_) - 1;                                                 \
            float v0_ = 0.f, v1_ = 0.f;                                               \
            if (hok_ && ww_ >= 0 && ww_ < W_IMG) {                                    \
                float mv_ = s_m[(r_) * 132 + m_ + (sc_)];                             \
                int c0_ = (ci0_) + j0_;                                               \
                if (c0_ < Cin)                                                        \
                    v0_ = g_pool[((n * Cin + c0_) * H + hh_) * W_IMG + ww_] * mv_;    \
                if (c0_ + 1 < Cin)                                                    \
                    v1_ = g_pool[((n * Cin + c0_ + 1) * H + hh_) * W_IMG + ww_] * mv_;\
            }                                                                         \
            *(__half2*)&sA[buf][m_ * LDA + j0_] = __floats2half2_rn(v0_, v1_);        \
        }                                                                             \
        const __half* wsrc_ = g_wTh + ((size_t)(tap_) * Cinp + (ci0_)) * CoutP + co0; \
        _Pragma("unroll")                                                             \
        for (int i_ = 0; i_ < 8; i_++) {                                              \
            int idx_ = (i_ << 8) + t;                                                 \
            int cp_ = idx_ & 63, k_ = idx_ >> 6;                                      \
            uint32_t v_ = *(const uint32_t*)&wsrc_[(size_t)k_ * CoutP + cp_ * 2];     \
            *(uint32_t*)&sB[buf][k_ * LDB + cp_ * 2] = v_;                            \
        }                                                                             \
    } while (0)

    float acc[4][4][4];
    #pragma unroll
    for (int mi = 0; mi < 4; mi++)
        #pragma unroll
        for (int ni = 0; ni < 4; ni++)
            #pragma unroll
            for (int q = 0; q < 4; q++) acc[mi][ni][q] = 0.f;

    // ldmatrix base addresses (per thread)
    const int rowX = lane & 15;
    const int colA = (lane >> 4) << 3;
    const uint32_t aoff0 = smem_u32(&sA[0][0]);
    const uint32_t boff0 = smem_u32(&sB[0][0]);
    const uint32_t a_rel = ((warp_m * 64 + rowX) * LDA + colA) * 2;
    const uint32_t b_rel = (rowX * LDB + warp_n * 32) * 2;
    const uint32_t abufsz = 128 * LDA * 2;
    const uint32_t bbufsz = 32 * LDB * 2;

    int tap = 0, rr = 0, sc = 0, ci0 = 0;
    STAGE(0, 0, 0, 0, 0);
    __syncthreads();

    for (int c = 0; c < chunks; c++) {
        // next-chunk params
        int ntap = tap, nci = ci0 + 32, nr = rr, nsc = sc;
        if (nci == Cinp) { nci = 0; ntap = tap + 1; nr = ntap / 3; nsc = ntap - nr * 3; }
        if (c + 1 < chunks) STAGE((c + 1) & 1, nr, nsc, nci, ntap);

        const uint32_t abase = aoff0 + (c & 1) * abufsz + a_rel;
        const uint32_t bbase = boff0 + (c & 1) * bbufsz + b_rel;

        #pragma unroll
        for (int kk = 0; kk < 2; kk++) {
            uint32_t a[4][4];
            #pragma unroll
            for (int mi = 0; mi < 4; mi++)
                LDMX4(a[mi][0], a[mi][1], a[mi][2], a[mi][3],
                      abase + (mi * 16 * LDA + kk * 16) * 2);
            uint32_t b[4][2];
            #pragma unroll
            for (int ni = 0; ni < 4; ni++)
                LDMX2T(b[ni][0], b[ni][1],
                       bbase + (kk * 16 * LDB + ni * 8) * 2);
            #pragma unroll
            for (int mi = 0; mi < 4; mi++)
                #pragma unroll
                for (int ni = 0; ni < 4; ni++)
                    MMA16816(acc[mi][ni], a[mi], b[ni]);
        }
        __syncthreads();
        tap = ntap; rr = nr; sc = nsc; ci0 = nci;
    }

    // ---- epilogue: scale/bias/zero + stores + stats ----
    const int gr = lane >> 2;
    const int gc = (lane & 3) * 2;
    float ssum[4][2], ssq[4][2];
    #pragma unroll
    for (int ni = 0; ni < 4; ni++)
        #pragma unroll
        for (int q = 0; q < 2; q++) { ssum[ni][q] = 0.f; ssq[ni][q] = 0.f; }

    #pragma unroll
    for (int mi = 0; mi < 4; mi++) {
        int m0 = warp_m * 64 + mi * 16 + gr;
        int m1 = m0 + 8;
        float sc0 = s_sc[m0], sc1 = s_sc[m1];
        bool nv0 = (s_nv[m0] != 0.f), nv1 = (s_nv[m1] != 0.f);
        #pragma unroll
        for (int ni = 0; ni < 4; ni++) {
            int colb = warp_n * 32 + ni * 8 + gc;
            #pragma unroll
            for (int q = 0; q < 2; q++) {
                int col = colb + q;
                int co = co0 + col;
                bool ok = (co < Cout);
                float bb = s_bi[col];
                float y0 = nv0 ? 0.f : fmaf(acc[mi][ni][q], sc0, bb);
                float y1 = nv1 ? 0.f : fmaf(acc[mi][ni][2 + q], sc1, bb);
                if (ok) {
                    int base = ((n * Cout + co) * H + h) * W_IMG;
                    g_conv[base + m0] = y0;
                    g_conv[base + m1] = y1;
                }
                ssum[ni][q] += y0 + y1;
                ssq[ni][q]  += y0 * y0 + y1 * y1;
            }
        }
    }
    #pragma unroll
    for (int ni = 0; ni < 4; ni++)
        #pragma unroll
        for (int q = 0; q < 2; q++) {
            float ss = ssum[ni][q], sq = ssq[ni][q];
            #pragma unroll
            for (int off = 4; off <= 16; off <<= 1) {
                ss += __shfl_xor_sync(0xffffffffu, ss, off);
                sq += __shfl_xor_sync(0xffffffffu, sq, off);
            }
            if (lane < 4) {
                int co = co0 + warp_n * 32 + ni * 8 + lane * 2 + q;
                if (co < Cout) {
                    atomicAdd(&g_stats[co], ss);
                    atomicAdd(&g_stats[Cout + co], sq);
                }
            }
        }
    #undef STAGE
}

// ---------------- fused BN + ReLU + 2x1 max pool (float4) ----------------
__global__ void bn_pool_kernel(const float* __restrict__ gamma,
                               const float* __restrict__ beta,
                               int Cout, int Hc)
{
    int idx = blockIdx.x * blockDim.x + threadIdx.x;
    int Hp = Hc >> 1;
    const int W4 = W_IMG / 4;
    int total = NB * Cout * Hp * W4;
    if (idx >= total) return;
    int w4 = idx % W4;
    int hp = (idx / W4) % Hp;
    int c  = (idx / (W4 * Hp)) % Cout;
    int n  = idx / (W4 * Hp * Cout);

    float cnt  = (float)(NB * Hc * W_IMG);
    float mean = g_stats[c] / cnt;
    float var  = g_stats[Cout + c] / cnt - mean * mean;
    float inv  = rsqrtf(var + 1e-5f);
    float ga = gamma[c], bb = beta[c];

    const float4* src = (const float4*)g_conv;
    int base = (((n * Cout + c) * Hc + 2 * hp) * W_IMG) / 4 + w4;
    float4 v0 = src[base];
    float4 v1 = src[base + W4];
    float4 o;
    o.x = fmaxf(fmaxf((v0.x - mean) * inv * ga + bb, 0.f), fmaxf((v1.x - mean) * inv * ga + bb, 0.f));
    o.y = fmaxf(fmaxf((v0.y - mean) * inv * ga + bb, 0.f), fmaxf((v1.y - mean) * inv * ga + bb, 0.f));
    o.z = fmaxf(fmaxf((v0.z - mean) * inv * ga + bb, 0.f), fmaxf((v1.z - mean) * inv * ga + bb, 0.f));
    o.w = fmaxf(fmaxf((v0.w - mean) * inv * ga + bb, 0.f), fmaxf((v1.w - mean) * inv * ga + bb, 0.f));
    ((float4*)g_pool)[((n * Cout + c) * Hp + hp) * W4 + w4] = o;
}

__global__ void mask_pool_kernel(int Hc) {
    int idx = blockIdx.x * blockDim.x + threadIdx.x;
    int Hp = Hc >> 1;
    int total = NB * Hp * W_IMG;
    if (idx >= total) return;
    int w  = idx % W_IMG;
    int hp = (idx / W_IMG) % Hp;
    int n  = idx / (W_IMG * Hp);
    int base = (n * Hc + 2 * hp) * W_IMG + w;
    g_maskA[(n * Hp + hp) * W_IMG + w] = fmaxf(g_maskB[base], g_maskB[base + W_IMG]);
}

// ---------------- head ----------------
__global__ void feat_kernel() {
    __shared__ float sred[128];
    int nc = blockIdx.x;
    const float* p = g_pool + (size_t)nc * 2048;
    float s = 0.f;
    for (int i = threadIdx.x; i < 2048; i += 128) s += p[i];
    sred[threadIdx.x] = s;
    __syncthreads();
    for (int o = 64; o; o >>= 1) {
        if (threadIdx.x < o) sred[threadIdx.x] += sred[threadIdx.x + o];
        __syncthreads();
    }
    if (threadIdx.x == 0) g_feat[nc] = sred[0] * (1.f / 2048.f);
}

__global__ void fc_kernel(const float* __restrict__ Wm, const float* __restrict__ b,
                          const float* __restrict__ in, float* __restrict__ out,
                          int IN, int OUT, int act)
{
    __shared__ float s[640];
    int n = blockIdx.x;
    for (int i = threadIdx.x; i < IN; i += blockDim.x) s[i] = in[n * IN + i];
    __syncthreads();
    int o = threadIdx.x;
    if (o < OUT) {
        float a = b[o];
        const float* wr = Wm + o * IN;
        for (int k = 0; k < IN; k++) a += wr[k] * s[k];
        if (act == 0) a = fmaxf(a, 0.f);
        else          a = 1.f / (1.f + expf(-a));
        out[n * OUT + o] = a;
    }
}

// ---------------- launch ----------------
extern "C" void kernel_launch(void* const* d_in, const int* in_sizes, int n_in,
                              void* d_out, int out_size)
{
    const float* x = (const float*)d_in[0];
    const float* w[4]  = {(const float*)d_in[1],  (const float*)d_in[5],
                          (const float*)d_in[9],  (const float*)d_in[13]};
    const float* bi[4] = {(const float*)d_in[2],  (const float*)d_in[6],
                          (const float*)d_in[10], (const float*)d_in[14]};
    const float* ga[4] = {(const float*)d_in[3],  (const float*)d_in[7],
                          (const float*)d_in[11], (const float*)d_in[15]};
    const float* be[4] = {(const float*)d_in[4],  (const float*)d_in[8],
                          (const float*)d_in[12], (const float*)d_in[16]};
    const float* fw1 = (const float*)d_in[17];
    const float* fb1 = (const float*)d_in[18];
    const float* fw2 = (const float*)d_in[19];
    const float* fb2 = (const float*)d_in[20];
    const float* hw  = (const float*)d_in[21];
    const float* hb  = (const float*)d_in[22];

    float *feat, *z1, *z2;
    cudaGetSymbolAddress((void**)&feat, g_feat);
    cudaGetSymbolAddress((void**)&z1,   g_z1);
    cudaGetSymbolAddress((void**)&z2,   g_z2);

    prep_kernel<<<(NB * 256 * 128 + 255) / 256, 256>>>(x);

    // ---- stage 1: scalar (Cin=1) ----
    {
        int Cout = 80, H = 256;
        zero_stats_kernel<<<1, 256>>>(2 * Cout);
        dim3 grid(H, 2, NB);
        pconv_kernel<<<grid, 256>>>(w[0], bi[0], 1, Cout, H);
        int Hp = H / 2;
        int tot4 = NB * Cout * Hp * (W_IMG / 4);
        bn_pool_kernel<<<(tot4 + 255) / 256, 256>>>(ga[0], be[0], Cout, H);
        mask_pool_kernel<<<(NB * Hp * W_IMG + 255) / 256, 256>>>(H);
    }

    // ---- stages 2-4: fp16 HMMA implicit GEMM ----
    int Cin = 80, H = 128;
    const int Couts[3] = {160, 320, 640};
    for (int s = 0; s < 3; s++) {
        int Cout = Couts[s];
        int Cinp = (Cin + 31) & ~31;
        int nT = (Cout + 127) / 128;
        int CoutP = nT * 128;

        int wtot = 9 * Cinp * CoutP;
        wprep_kernel<<<(wtot + 255) / 256, 256>>>(w[s + 1], Cin, Cinp, Cout, CoutP);
        zero_stats_kernel<<<(2 * Cout + 255) / 256, 256>>>(2 * Cout);

        dim3 grid(NB * H, nT);
        pconv_hmma_kernel<<<grid, 256>>>(bi[s + 1], Cin, Cinp, Cout, H);

        int Hp = H / 2;
        int tot4 = NB * Cout * Hp * (W_IMG / 4);
        bn_pool_kernel<<<(tot4 + 255) / 256, 256>>>(ga[s + 1], be[s + 1], Cout, H);
        mask_pool_kernel<<<(NB * Hp * W_IMG + 255) / 256, 256>>>(H);
        Cin = Cout; H = Hp;
    }

    feat_kernel<<<NB * 640, 128>>>();
    fc_kernel<<<NB, 256>>>(fw1, fb1, feat, z1, 640, 256, 0);
    fc_kernel<<<NB, 256>>>(fw2, fb2, z1, z2, 256, 128, 0);
    fc_kernel<<<NB, 128>>>(hw, hb, z2, (float*)d_out, 128, 1, 1);
}

// round 5
// speedup vs baseline: 6.2377x; 2.1243x over previous
#include <cuda_runtime.h>
#include <cuda_fp16.h>
#include <math.h>
#include <stdint.h>

#define W_IMG 128
#define NB 16
#define LDA 40      // A smem stride in halves (80B rows: 16B-aligned, conflict-free ldmatrix)
#define LDB 136     // B smem stride in halves (272B rows)

// ---------------- scratch (static device globals; no allocation) ----------------
__device__ float  g_conv[41943040];   // conv output per stage
__device__ float  g_pool[20971520];   // pooled fp32 output / next-stage input
__device__ float  g_maskA[524288];    // stage input mask (N,1,H,W)
__device__ float  g_maskB[524288];    // full-res mask_next before pooling
__device__ float  g_stats[1280];      // [sum(0..C), sumsq(C..2C)]
__device__ __half g_wTh[1843200];     // transposed+padded fp16 weights [tap][ciP][coP]
__device__ __half g_xmh[25165824];    // fp16 premasked transposed input [n][h][w][ciP]
__device__ float  g_feat[NB * 640];
__device__ float  g_z1[NB * 256];
__device__ float  g_z2[NB * 128];

__device__ __forceinline__ uint32_t smem_u32(const void* p) {
    uint32_t a;
    asm("{ .reg .u64 t; cvta.to.shared.u64 t, %1; cvt.u32.u64 %0, t; }" : "=r"(a) : "l"(p));
    return a;
}
__device__ __forceinline__ void cpa16(uint32_t dst, const void* src, uint32_t sz) {
    asm volatile("cp.async.cg.shared.global [%0], [%1], 16, %2;"
                 :: "r"(dst), "l"(src), "r"(sz) : "memory");
}
#define CP_COMMIT() asm volatile("cp.async.commit_group;" ::: "memory")
#define CP_WAIT1()  asm volatile("cp.async.wait_group 1;" ::: "memory")

#define LDMX4(r0, r1, r2, r3, addr) \
    asm volatile("ldmatrix.sync.aligned.m8n8.x4.shared.b16 {%0,%1,%2,%3}, [%4];" \
                 : "=r"(r0), "=r"(r1), "=r"(r2), "=r"(r3) : "r"(addr))
#define LDMX2T(r0, r1, addr) \
    asm volatile("ldmatrix.sync.aligned.m8n8.x2.trans.shared.b16 {%0,%1}, [%2];" \
                 : "=r"(r0), "=r"(r1) : "r"(addr))
#define MMA16816(d, a, b) \
    asm volatile("mma.sync.aligned.m16n8k16.row.col.f32.f16.f16.f32 " \
                 "{%0,%1,%2,%3}, {%4,%5,%6,%7}, {%8,%9}, {%0,%1,%2,%3};" \
                 : "+f"((d)[0]), "+f"((d)[1]), "+f"((d)[2]), "+f"((d)[3]) \
                 : "r"((a)[0]), "r"((a)[1]), "r"((a)[2]), "r"((a)[3]), \
                   "r"((b)[0]), "r"((b)[1]))

// dynamic smem layout (bytes)
#define OFF_A   0
#define ABUF    (128 * LDA * 2)          // 10240
#define OFF_B   (3 * ABUF)               // 30720
#define BBUF    (32 * LDB * 2)           // 8704
#define OFF_M   (OFF_B + 3 * BBUF)       // 56832
#define OFF_SC  (OFF_M + 1584)           // 58416
#define OFF_NV  (OFF_SC + 512)           // 58928
#define OFF_BI  (OFF_NV + 512)           // 59440
#define SM_TOT  (OFF_BI + 512)           // 59952

// ---------------- prep: split data / clipped mask ----------------
__global__ void prep_kernel(const float* __restrict__ x) {
    int idx = blockIdx.x * blockDim.x + threadIdx.x;
    const int per = 256 * 128;
    if (idx >= NB * per) return;
    int n = idx / per;
    int rest = idx - n * per;
    g_pool[idx] = x[(n * 2 + 0) * per + rest];
    float m = x[(n * 2 + 1) * per + rest];
    g_maskA[idx] = fminf(fmaxf(m, 0.f), 1.f);
}

__global__ void zero_stats_kernel(int n) {
    int i = blockIdx.x * blockDim.x + threadIdx.x;
    if (i < n) g_stats[i] = 0.f;
}

// ---------------- weight transpose+pad: wts[co][ci][tap] -> g_wTh[tap][ci][co] ----------------
__global__ void wprep_kernel(const float* __restrict__ wts,
                             int Cin, int Cinp, int Cout, int CoutP) {
    int idx = blockIdx.x * blockDim.x + threadIdx.x;
    int total = 9 * Cinp * CoutP;
    if (idx >= total) return;
    int tap = idx / (Cinp * CoutP);
    int rem = idx - tap * (Cinp * CoutP);
    int ci = rem / CoutP;
    int co = rem - ci * CoutP;
    float v = 0.f;
    if (ci < Cin && co < Cout) v = wts[(co * Cin + ci) * 9 + tap];
    g_wTh[idx] = __float2half(v);
}

// ---------------- input transpose+mask+fp16: g_pool[n][c][h][w] -> g_xmh[n][h][w][ciP] ----------------
__global__ void xm_kernel(int Cin, int Cinp, int H) {
    __shared__ __half tile[32][33];
    int nh = blockIdx.z;
    int n = nh / H;
    int w0 = blockIdx.x * 32, c0 = blockIdx.y * 32;
    int tx = threadIdx.x, ty = threadIdx.y;   // 32 x 8
    float m = g_maskA[nh * W_IMG + w0 + tx];
    #pragma unroll
    for (int j = 0; j < 4; j++) {
        int cl = ty + j * 8;
        int ci = c0 + cl;
        float v = 0.f;
        if (ci < Cin)
            v = g_pool[((size_t)(n * Cin + ci) * H + (nh % H)) * W_IMG + w0 + tx] * m;
        tile[cl][tx] = __float2half(v);
    }
    __syncthreads();
    #pragma unroll
    for (int j = 0; j < 4; j++) {
        int wl = ty + j * 8;
        g_xmh[((size_t)nh * W_IMG + w0 + wl) * Cinp + c0 + tx] = tile[tx][wl];
    }
}

// ---------------- stage-1 scalar partial conv (proven, Cin=1) ----------------
__launch_bounds__(256)
__global__ void pconv_kernel(const float* __restrict__ wts,
                             const float* __restrict__ bias,
                             int Cin, int Cout, int H)
{
    __shared__ __align__(16) float s_in[8][3][132];
    __shared__ __align__(16) float s_m[3][132];
    __shared__ __align__(16) float s_w[8][9][64];

    const int t    = threadIdx.x;
    const int h    = blockIdx.x;
    const int co0  = blockIdx.y * 64;
    const int n    = blockIdx.z;
    const int pxg  = t & 31;
    const int cog  = t >> 5;
    const int px0  = pxg * 4;
    const int lane = t & 31;

    for (int idx = t; idx < 3 * 130; idx += 256) {
        int r = idx / 130, col = idx % 130;
        int hh = h - 1 + r, ww = col - 1;
        float v = 1.0f;
        if (hh >= 0 && hh < H && ww >= 0 && ww < W_IMG)
            v = g_maskA[(n * H + hh) * W_IMG + ww];
        s_m[r][col] = v;
    }
    __syncthreads();

    float msum[4];
    #pragma unroll
    for (int p = 0; p < 4; p++) {
        float s = 0.f;
        #pragma unroll
        for (int r = 0; r < 3; r++)
            #pragma unroll
            for (int tw = 0; tw < 3; tw++)
                s += s_m[r][px0 + p + tw];
        msum[p] = s;
    }

    float acc[8][4];
    #pragma unroll
    for (int j = 0; j < 8; j++)
        #pragma unroll
        for (int p = 0; p < 4; p++) acc[j][p] = 0.f;

    for (int ci0 = 0; ci0 < Cin; ci0 += 8) {
        __syncthreads();
        for (int idx = t; idx < 8 * 3 * 130; idx += 256) {
            int c = idx / 390, rem = idx - c * 390;
            int r = rem / 130, col = rem - r * 130;
            int hh = h - 1 + r, ww = col - 1;
            int ci = ci0 + c;
            float v = 0.f;
            if (ci < Cin && hh >= 0 && hh < H && ww >= 0 && ww < W_IMG)
                v = g_pool[((n * Cin + ci) * H + hh) * W_IMG + ww] * s_m[r][col];
            s_in[c][r][col] = v;
        }
        for (int idx = t; idx < 8 * 9 * 64; idx += 256) {
            int c = idx / 576, rem = idx - c * 576;
            int tap = rem / 64, co = rem - tap * 64;
            int gco = co0 + co, ci = ci0 + c;
            float v = 0.f;
            if (gco < Cout && ci < Cin)
                v = wts[(gco * Cin + ci) * 9 + tap];
            s_w[c][tap][co] = v;
        }
        __syncthreads();

        #pragma unroll
        for (int c = 0; c < 8; c++) {
            #pragma unroll
            for (int r = 0; r < 3; r++) {
                float iv[6];
                #pragma unroll
                for (int k = 0; k < 6; k++) iv[k] = s_in[c][r][px0 + k];
                #pragma unroll
                for (int tw = 0; tw < 3; tw++) {
                    float4 wA = *(const float4*)&s_w[c][r * 3 + tw][cog * 8];
                    float4 wB = *(const float4*)&s_w[c][r * 3 + tw][cog * 8 + 4];
                    float wj[8] = {wA.x, wA.y, wA.z, wA.w, wB.x, wB.y, wB.z, wB.w};
                    #pragma unroll
                    for (int j = 0; j < 8; j++)
                        #pragma unroll
                        for (int p = 0; p < 4; p++)
                            acc[j][p] += wj[j] * iv[tw + p];
                }
            }
        }
    }

    float scale[4];
    bool  nov[4];
    #pragma unroll
    for (int p = 0; p < 4; p++) {
        float valid = (float)Cin * msum[p];
        nov[p]   = (valid <= 0.f);
        scale[p] = (float)(Cin * 9) / fmaxf(valid, 1.0f);
    }
    if (blockIdx.y == 0 && cog == 0) {
        #pragma unroll
        for (int p = 0; p < 4; p++)
            g_maskB[(n * H + h) * W_IMG + px0 + p] = nov[p] ? 0.f : 1.f;
    }

    #pragma unroll
    for (int j = 0; j < 8; j++) {
        int gco = co0 + cog * 8 + j;
        bool ok = (gco < Cout);
        float b = ok ? bias[gco] : 0.f;
        float ssum = 0.f, ssq = 0.f;
        #pragma unroll
        for (int p = 0; p < 4; p++) {
            float y = nov[p] ? 0.f : (acc[j][p] * scale[p] + b);
            if (ok) g_conv[((n * Cout + gco) * H + h) * W_IMG + px0 + p] = y;
            ssum += y;
            ssq  += y * y;
        }
        #pragma unroll
        for (int off = 16; off; off >>= 1) {
            ssum += __shfl_xor_sync(0xffffffffu, ssum, off);
            ssq  += __shfl_xor_sync(0xffffffffu, ssq,  off);
        }
        if (lane == 0 && ok) {
            atomicAdd(&g_stats[gco], ssum);
            atomicAdd(&g_stats[Cout + gco], ssq);
        }
    }
}

// ---------------- fp16 HMMA implicit-GEMM partial conv, cp.async 3-ring ----------------
// CTA: M=128 px (one (n,h) row) x N=128 cout. 8 warps = 2(M) x 4(N), warp tile 64x32.
__launch_bounds__(256, 2)
__global__ void pconv_hmma_kernel(const float* __restrict__ bias,
                                  int Cin, int Cinp, int Cout, int H)
{
    extern __shared__ char smem[];
    const uint32_t sb = smem_u32(smem);
    float* s_m  = (float*)(smem + OFF_M);
    float* s_sc = (float*)(smem + OFF_SC);
    float* s_nv = (float*)(smem + OFF_NV);
    float* s_bi = (float*)(smem + OFF_BI);

    const int t    = threadIdx.x;
    const int wid  = t >> 5;
    const int lane = t & 31;
    const int h    = blockIdx.x % H;
    const int n    = blockIdx.x / H;
    const int co0  = blockIdx.y * 128;
    const int CoutP = gridDim.y * 128;
    const int warp_m = wid & 1;
    const int warp_n = wid >> 1;

    // ---- mask rows (OOB = 1.0) + bias ----
    for (int idx = t; idx < 3 * 130; idx += 256) {
        int r = idx / 130, col = idx % 130;
        int hh = h - 1 + r, ww = col - 1;
        float v = 1.0f;
        if (hh >= 0 && hh < H && ww >= 0 && ww < W_IMG)
            v = g_maskA[(n * H + hh) * W_IMG + ww];
        s_m[r * 132 + col] = v;
    }
    if (t < 128) s_bi[t] = (co0 + t < Cout) ? bias[co0 + t] : 0.f;
    __syncthreads();

    if (t < 128) {
        float s = 0.f;
        #pragma unroll
        for (int r = 0; r < 3; r++)
            #pragma unroll
            for (int tw = 0; tw < 3; tw++)
                s += s_m[r * 132 + t + tw];
        float valid = (float)Cin * s;
        s_nv[t] = (valid <= 0.f) ? 1.f : 0.f;
        s_sc[t] = (float)(Cin * 9) / fmaxf(valid, 1.0f);
        if (blockIdx.y == 0)
            g_maskB[(n * H + h) * W_IMG + t] = (valid <= 0.f) ? 0.f : 1.f;
    }

    const int CPT = Cinp >> 5;
    const int chunks = 9 * CPT;

    // ---- cp.async chunk issue: A (im2col row) + B (weights) ----
    auto issue = [&](int c) {
        int buf = c % 3;
        int tap = c / CPT;
        int ci0 = (c - tap * CPT) << 5;
        int r = tap / 3, sc = tap - r * 3;
        int hh = h - 1 + r;
        bool hok = (hh >= 0 && hh < H);
        const uint32_t abase = sb + OFF_A + buf * ABUF;
        const uint32_t bbase = sb + OFF_B + buf * BBUF;
        #pragma unroll
        for (int i = 0; i < 2; i++) {
            int op = t + (i << 8);
            int m = op >> 2, seg = op & 3;
            int ww = m + sc - 1;
            bool ok = hok && ((unsigned)ww < W_IMG);
            const __half* src = ok
                ? &g_xmh[((size_t)(n * H + hh) * W_IMG + ww) * Cinp + ci0 + seg * 8]
                : g_xmh;
            cpa16(abase + (m * LDA + seg * 8) * 2, src, ok ? 16u : 0u);
        }
        const __half* wsrc = g_wTh + ((size_t)tap * Cinp + ci0) * CoutP + co0;
        #pragma unroll
        for (int i = 0; i < 2; i++) {
            int op = t + (i << 8);
            int k = op >> 4, seg = op & 15;
            cpa16(bbase + k * LDB * 2 + seg * 16, wsrc + (size_t)k * CoutP + seg * 8, 16u);
        }
        CP_COMMIT();
    };

    float acc[4][4][4];
    #pragma unroll
    for (int mi = 0; mi < 4; mi++)
        #pragma unroll
        for (int ni = 0; ni < 4; ni++)
            #pragma unroll
            for (int q = 0; q < 4; q++) acc[mi][ni][q] = 0.f;

    const int rowX = lane & 15;
    const int colA = (lane >> 4) << 3;
    const uint32_t a_rel = ((warp_m * 64 + rowX) * LDA + colA) * 2;
    const uint32_t b_rel = (rowX * LDB + warp_n * 32) * 2;

    issue(0);
    if (chunks > 1) issue(1);

    for (int c = 0; c < chunks; c++) {
        CP_WAIT1();
        __syncthreads();
        if (c + 2 < chunks) issue(c + 2);

        const int buf = c % 3;
        const uint32_t abase = sb + OFF_A + buf * ABUF + a_rel;
        const uint32_t bbase = sb + OFF_B + buf * BBUF + b_rel;

        #pragma unroll
        for (int kk = 0; kk < 2; kk++) {
            uint32_t a[4][4];
            #pragma unroll
            for (int mi = 0; mi < 4; mi++)
                LDMX4(a[mi][0], a[mi][1], a[mi][2], a[mi][3],
                      abase + (mi * 16 * LDA + kk * 16) * 2);
            uint32_t b[4][2];
            #pragma unroll
            for (int ni = 0; ni < 4; ni++)
                LDMX2T(b[ni][0], b[ni][1],
                       bbase + (kk * 16 * LDB + ni * 8) * 2);
            #pragma unroll
            for (int mi = 0; mi < 4; mi++)
                #pragma unroll
                for (int ni = 0; ni < 4; ni++)
                    MMA16816(acc[mi][ni], a[mi], b[ni]);
        }
        __syncthreads();
    }

    // ---- epilogue: scale/bias/zero + stores + stats ----
    const int gr = lane >> 2;
    const int gc = (lane & 3) * 2;
    float ssum[4][2], ssq[4][2];
    #pragma unroll
    for (int ni = 0; ni < 4; ni++)
        #pragma unroll
        for (int q = 0; q < 2; q++) { ssum[ni][q] = 0.f; ssq[ni][q] = 0.f; }

    #pragma unroll
    for (int mi = 0; mi < 4; mi++) {
        int m0 = warp_m * 64 + mi * 16 + gr;
        int m1 = m0 + 8;
        float sc0 = s_sc[m0], sc1 = s_sc[m1];
        bool nv0 = (s_nv[m0] != 0.f), nv1 = (s_nv[m1] != 0.f);
        #pragma unroll
        for (int ni = 0; ni < 4; ni++) {
            int colb = warp_n * 32 + ni * 8 + gc;
            #pragma unroll
            for (int q = 0; q < 2; q++) {
                int col = colb + q;
                int co = co0 + col;
                bool ok = (co < Cout);
                float bb = s_bi[col];
                float y0 = nv0 ? 0.f : fmaf(acc[mi][ni][q], sc0, bb);
                float y1 = nv1 ? 0.f : fmaf(acc[mi][ni][2 + q], sc1, bb);
                if (ok) {
                    int base = ((n * Cout + co) * H + h) * W_IMG;
                    g_conv[base + m0] = y0;
                    g_conv[base + m1] = y1;
                }
                ssum[ni][q] += y0 + y1;
                ssq[ni][q]  += y0 * y0 + y1 * y1;
            }
        }
    }
    #pragma unroll
    for (int ni = 0; ni < 4; ni++)
        #pragma unroll
        for (int q = 0; q < 2; q++) {
            float ss = ssum[ni][q], sq = ssq[ni][q];
            #pragma unroll
            for (int off = 4; off <= 16; off <<= 1) {
                ss += __shfl_xor_sync(0xffffffffu, ss, off);
                sq += __shfl_xor_sync(0xffffffffu, sq, off);
            }
            if (lane < 4) {
                int co = co0 + warp_n * 32 + ni * 8 + lane * 2 + q;
                if (co < Cout) {
                    atomicAdd(&g_stats[co], ss);
                    atomicAdd(&g_stats[Cout + co], sq);
                }
            }
        }
}

// ---------------- fused BN + ReLU + 2x1 max pool (float4) ----------------
__global__ void bn_pool_kernel(const float* __restrict__ gamma,
                               const float* __restrict__ beta,
                               int Cout, int Hc)
{
    int idx = blockIdx.x * blockDim.x + threadIdx.x;
    int Hp = Hc >> 1;
    const int W4 = W_IMG / 4;
    int total = NB * Cout * Hp * W4;
    if (idx >= total) return;
    int w4 = idx % W4;
    int hp = (idx / W4) % Hp;
    int c  = (idx / (W4 * Hp)) % Cout;
    int n  = idx / (W4 * Hp * Cout);

    float cnt  = (float)(NB * Hc * W_IMG);
    float mean = g_stats[c] / cnt;
    float var  = g_stats[Cout + c] / cnt - mean * mean;
    float inv  = rsqrtf(var + 1e-5f);
    float ga = gamma[c], bb = beta[c];

    const float4* src = (const float4*)g_conv;
    int base = (((n * Cout + c) * Hc + 2 * hp) * W_IMG) / 4 + w4;
    float4 v0 = src[base];
    float4 v1 = src[base + W4];
    float4 o;
    o.x = fmaxf(fmaxf((v0.x - mean) * inv * ga + bb, 0.f), fmaxf((v1.x - mean) * inv * ga + bb, 0.f));
    o.y = fmaxf(fmaxf((v0.y - mean) * inv * ga + bb, 0.f), fmaxf((v1.y - mean) * inv * ga + bb, 0.f));
    o.z = fmaxf(fmaxf((v0.z - mean) * inv * ga + bb, 0.f), fmaxf((v1.z - mean) * inv * ga + bb, 0.f));
    o.w = fmaxf(fmaxf((v0.w - mean) * inv * ga + bb, 0.f), fmaxf((v1.w - mean) * inv * ga + bb, 0.f));
    ((float4*)g_pool)[((n * Cout + c) * Hp + hp) * W4 + w4] = o;
}

__global__ void mask_pool_kernel(int Hc) {
    int idx = blockIdx.x * blockDim.x + threadIdx.x;
    int Hp = Hc >> 1;
    int total = NB * Hp * W_IMG;
    if (idx >= total) return;
    int w  = idx % W_IMG;
    int hp = (idx / W_IMG) % Hp;
    int n  = idx / (W_IMG * Hp);
    int base = (n * Hc + 2 * hp) * W_IMG + w;
    g_maskA[(n * Hp + hp) * W_IMG + w] = fmaxf(g_maskB[base], g_maskB[base + W_IMG]);
}

// ---------------- head ----------------
__global__ void feat_kernel() {
    __shared__ float sred[128];
    int nc = blockIdx.x;
    const float* p = g_pool + (size_t)nc * 2048;
    float s = 0.f;
    for (int i = threadIdx.x; i < 2048; i += 128) s += p[i];
    sred[threadIdx.x] = s;
    __syncthreads();
    for (int o = 64; o; o >>= 1) {
        if (threadIdx.x < o) sred[threadIdx.x] += sred[threadIdx.x + o];
        __syncthreads();
    }
    if (threadIdx.x == 0) g_feat[nc] = sred[0] * (1.f / 2048.f);
}

__global__ void fc_kernel(const float* __restrict__ Wm, const float* __restrict__ b,
                          const float* __restrict__ in, float* __restrict__ out,
                          int IN, int OUT, int act)
{
    __shared__ float s[640];
    int n = blockIdx.x;
    for (int i = threadIdx.x; i < IN; i += blockDim.x) s[i] = in[n * IN + i];
    __syncthreads();
    int o = threadIdx.x;
    if (o < OUT) {
        float a = b[o];
        const float* wr = Wm + o * IN;
        for (int k = 0; k < IN; k++) a += wr[k] * s[k];
        if (act == 0) a = fmaxf(a, 0.f);
        else          a = 1.f / (1.f + expf(-a));
        out[n * OUT + o] = a;
    }
}

// ---------------- launch ----------------
extern "C" void kernel_launch(void* const* d_in, const int* in_sizes, int n_in,
                              void* d_out, int out_size)
{
    const float* x = (const float*)d_in[0];
    const float* w[4]  = {(const float*)d_in[1],  (const float*)d_in[5],
                          (const float*)d_in[9],  (const float*)d_in[13]};
    const float* bi[4] = {(const float*)d_in[2],  (const float*)d_in[6],
                          (const float*)d_in[10], (const float*)d_in[14]};
    const float* ga[4] = {(const float*)d_in[3],  (const float*)d_in[7],
                          (const float*)d_in[11], (const float*)d_in[15]};
    const float* be[4] = {(const float*)d_in[4],  (const float*)d_in[8],
                          (const float*)d_in[12], (const float*)d_in[16]};
    const float* fw1 = (const float*)d_in[17];
    const float* fb1 = (const float*)d_in[18];
    const float* fw2 = (const float*)d_in[19];
    const float* fb2 = (const float*)d_in[20];
    const float* hw  = (const float*)d_in[21];
    const float* hb  = (const float*)d_in[22];

    cudaFuncSetAttribute(pconv_hmma_kernel,
                         cudaFuncAttributeMaxDynamicSharedMemorySize, SM_TOT);

    float *feat, *z1, *z2;
    cudaGetSymbolAddress((void**)&feat, g_feat);
    cudaGetSymbolAddress((void**)&z1,   g_z1);
    cudaGetSymbolAddress((void**)&z2,   g_z2);

    prep_kernel<<<(NB * 256 * 128 + 255) / 256, 256>>>(x);

    // ---- stage 1: scalar (Cin=1) ----
    {
        int Cout = 80, H = 256;
        zero_stats_kernel<<<1, 256>>>(2 * Cout);
        dim3 grid(H, 2, NB);
        pconv_kernel<<<grid, 256>>>(w[0], bi[0], 1, Cout, H);
        int Hp = H / 2;
        mask_pool_kernel<<<(NB * Hp * W_IMG + 255) / 256, 256>>>(H);
        int tot4 = NB * Cout * Hp * (W_IMG / 4);
        bn_pool_kernel<<<(tot4 + 255) / 256, 256>>>(ga[0], be[0], Cout, H);
    }

    // ---- stages 2-4: fp16 HMMA implicit GEMM with cp.async ring ----
    int Cin = 80, H = 128;
    const int Couts[3] = {160, 320, 640};
    for (int s = 0; s < 3; s++) {
        int Cout = Couts[s];
        int Cinp = (Cin + 31) & ~31;
        int nT = (Cout + 127) / 128;
        int CoutP = nT * 128;

        // transpose+mask+fp16 input for this stage
        {
            dim3 tg(4, Cinp / 32, NB * H);
            dim3 tb(32, 8);
            xm_kernel<<<tg, tb>>>(Cin, Cinp, H);
        }
        int wtot = 9 * Cinp * CoutP;
        wprep_kernel<<<(wtot + 255) / 256, 256>>>(w[s + 1], Cin, Cinp, Cout, CoutP);
        zero_stats_kernel<<<(2 * Cout + 255) / 256, 256>>>(2 * Cout);

        dim3 grid(NB * H, nT);
        pconv_hmma_kernel<<<grid, 256, SM_TOT>>>(bi[s + 1], Cin, Cinp, Cout, H);

        int Hp = H / 2;
        mask_pool_kernel<<<(NB * Hp * W_IMG + 255) / 256, 256>>>(H);
        int tot4 = NB * Cout * Hp * (W_IMG / 4);
        bn_pool_kernel<<<(tot4 + 255) / 256, 256>>>(ga[s + 1], be[s + 1], Cout, H);
        Cin = Cout; H = Hp;
    }

    feat_kernel<<<NB * 640, 128>>>();
    fc_kernel<<<NB, 256>>>(fw1, fb1, feat, z1, 640, 256, 0);
    fc_kernel<<<NB, 256>>>(fw2, fb2, z1, z2, 256, 128, 0);
    fc_kernel<<<NB, 128>>>(hw, hb, z2, (float*)d_out, 128, 1, 1);
}